// round 2
// baseline (speedup 1.0000x reference)
#include <cuda_runtime.h>
#include <cuda_bf16.h>
#include <cstdint>

// Problem shape (fixed by the dataset): B=64, T=1000, I=512, O=256
#define SNN_B 64
#define SNN_T 1000
#define SNN_I 512
#define SNN_O 256
#define ALPHA 0.95f
#define BETA  0.9f

// Scratch for h = inputs @ W^T : (B*T, O) fp32 = 65.5 MB (device global; no runtime alloc)
__device__ float g_h[(size_t)SNN_B * SNN_T * SNN_O];

// ---------------------------------------------------------------------------
// Kernel 1: SGEMM  H[m][n] = sum_k A[m][k] * W[n][k]
//   A: (64000, 512) row-major (k contiguous), W: (256, 512) row-major (k contiguous)
//   Tile: BM=128, BN=128, BK=8, 256 threads, 8x8 microtile per thread.
// ---------------------------------------------------------------------------
#define BM 128
#define BN 128
#define BK 8
#define SMPAD 4  // pad rows to 132 floats = 528B (multiple of 16B -> float4-safe)

__global__ __launch_bounds__(256)
void snn_gemm_kernel(const float* __restrict__ A,
                     const float* __restrict__ W,
                     float* __restrict__ H)
{
    __shared__ float As[BK][BM + SMPAD];
    __shared__ float Bs[BK][BN + SMPAD];

    const int bm = blockIdx.x * BM;      // 500 tiles over M=64000
    const int bn = blockIdx.y * BN;      // 2 tiles over N=256
    const int tid = threadIdx.x;         // 256 threads
    const int tx = tid & 15;             // n-dim: 16 groups * 8 cols
    const int ty = tid >> 4;             // m-dim: 16 groups * 8 rows

    // Global->shared load mapping: 1 float4 of A and 1 float4 of W per thread per K-tile
    const int lm = tid >> 1;             // 0..127 row within tile
    const int lk = (tid & 1) * 4;        // 0 or 4

    const float* Aptr = A + (size_t)(bm + lm) * SNN_I + lk;
    const float* Bptr = W + (size_t)(bn + lm) * SNN_I + lk;

    float acc[8][8];
    #pragma unroll
    for (int i = 0; i < 8; i++)
        #pragma unroll
        for (int j = 0; j < 8; j++)
            acc[i][j] = 0.0f;

    for (int k0 = 0; k0 < SNN_I; k0 += BK) {
        float4 av = *reinterpret_cast<const float4*>(Aptr + k0);
        float4 bv = *reinterpret_cast<const float4*>(Bptr + k0);

        As[lk + 0][lm] = av.x;
        As[lk + 1][lm] = av.y;
        As[lk + 2][lm] = av.z;
        As[lk + 3][lm] = av.w;
        Bs[lk + 0][lm] = bv.x;
        Bs[lk + 1][lm] = bv.y;
        Bs[lk + 2][lm] = bv.z;
        Bs[lk + 3][lm] = bv.w;
        __syncthreads();

        #pragma unroll
        for (int kk = 0; kk < BK; kk++) {
            float4 a0 = *reinterpret_cast<const float4*>(&As[kk][ty * 8]);
            float4 a1 = *reinterpret_cast<const float4*>(&As[kk][ty * 8 + 4]);
            float4 b0 = *reinterpret_cast<const float4*>(&Bs[kk][tx * 8]);
            float4 b1 = *reinterpret_cast<const float4*>(&Bs[kk][tx * 8 + 4]);
            float a[8] = {a0.x, a0.y, a0.z, a0.w, a1.x, a1.y, a1.z, a1.w};
            float b[8] = {b0.x, b0.y, b0.z, b0.w, b1.x, b1.y, b1.z, b1.w};
            #pragma unroll
            for (int i = 0; i < 8; i++)
                #pragma unroll
                for (int j = 0; j < 8; j++)
                    acc[i][j] = fmaf(a[i], b[j], acc[i][j]);
        }
        __syncthreads();
    }

    // Write H tile: rows contiguous in n -> 2x float4 per row
    #pragma unroll
    for (int i = 0; i < 8; i++) {
        float* hrow = H + (size_t)(bm + ty * 8 + i) * SNN_O + (bn + tx * 8);
        float4 v0 = {acc[i][0], acc[i][1], acc[i][2], acc[i][3]};
        float4 v1 = {acc[i][4], acc[i][5], acc[i][6], acc[i][7]};
        *reinterpret_cast<float4*>(hrow)     = v0;
        *reinterpret_cast<float4*>(hrow + 4) = v1;
    }
}

// ---------------------------------------------------------------------------
// Kernel 2: per-(b,o) 2-state linear scan over T=1000.
//   flt' = ALPHA*flt + h_t ; out' = BETA*out + flt(old) ; emit out'
//   16384 independent chains; batch 8 loads per iteration for MLP.
//   Warp lanes cover consecutive o -> 128B-coalesced loads/stores per t.
// ---------------------------------------------------------------------------
__global__ __launch_bounds__(128)
void snn_scan_kernel(const float* __restrict__ H, float* __restrict__ out)
{
    const int idx = blockIdx.x * blockDim.x + threadIdx.x;  // 0..16383
    const int b = idx >> 8;          // / 256
    const int o = idx & 255;         // % 256

    const float* hp = H   + (size_t)b * SNN_T * SNN_O + o;
    float*       op = out + (size_t)b * SNN_T * SNN_O + o;

    float flt = 0.0f, acc = 0.0f;

    #pragma unroll 1
    for (int t = 0; t < SNN_T; t += 8) {
        float v[8];
        #pragma unroll
        for (int j = 0; j < 8; j++)
            v[j] = __ldg(hp + (size_t)(t + j) * SNN_O);
        #pragma unroll
        for (int j = 0; j < 8; j++) {
            float nf = fmaf(ALPHA, flt, v[j]);
            acc = fmaf(BETA, acc, flt);   // uses OLD flt
            flt = nf;
            op[(size_t)(t + j) * SNN_O] = acc;
        }
    }
}

// ---------------------------------------------------------------------------
// Launch
// ---------------------------------------------------------------------------
extern "C" void kernel_launch(void* const* d_in, const int* in_sizes, int n_in,
                              void* d_out, int out_size)
{
    const float* inputs = (const float*)d_in[0];   // (B, T, I)
    const float* W      = (const float*)d_in[1];   // (O, I)
    // d_in[2] = nb_steps (int32, == SNN_T), unused on device

    float* out = (float*)d_out;                    // (B, T, O)

    float* h;
    cudaGetSymbolAddress((void**)&h, g_h);

    dim3 gemm_grid(SNN_B * SNN_T / BM, SNN_O / BN);  // (500, 2)
    snn_gemm_kernel<<<gemm_grid, 256>>>(inputs, W, h);

    const int chains = SNN_B * SNN_O;                // 16384
    snn_scan_kernel<<<chains / 128, 128>>>(h, out);
}

// round 3
// speedup vs baseline: 2.6237x; 2.6237x over previous
#include <cuda_runtime.h>
#include <cuda_bf16.h>
#include <cstdint>

// Problem shape (fixed): B=64, T=1000, I=512, O=256
#define SNN_B 64
#define SNN_T 1000
#define SNN_I 512
#define SNN_O 256
#define ALPHA 0.95f
#define BETA  0.9f

#define CHUNKS 8
#define CHUNK_L 125          // 8 * 125 = 1000
#define CHAINS (SNN_B * SNN_O)   // 16384

// Scratch: h = inputs @ W^T (65.5 MB) + per-chunk states (device globals; no runtime alloc)
__device__ float  g_h[(size_t)SNN_B * SNN_T * SNN_O];
__device__ float2 g_end [CHAINS * CHUNKS];   // local-scan final states
__device__ float2 g_init[CHAINS * CHUNKS];   // corrected initial states

// ---------------------------------------------------------------------------
// TF32 helpers
// ---------------------------------------------------------------------------
__device__ __forceinline__ uint32_t f2tf32(float x) {
    uint32_t r;
    asm("cvt.rna.tf32.f32 %0, %1;" : "=r"(r) : "f"(x));
    return r;
}

// ---------------------------------------------------------------------------
// Kernel 1: TF32 tensor-core GEMM  H[m][n] = sum_k A[m][k] * W[n][k]
//   A: (64000, 512), W: (256, 512), both k-contiguous.
//   Block tile 128x128x32, 256 threads (8 warps, 4x2), warp tile 32x64.
//   mma.sync.aligned.m16n8k8.row.col.f32.tf32.tf32.f32
// ---------------------------------------------------------------------------
#define GBM 128
#define GBN 128
#define GBK 32
#define KSTR (GBK + 4)   // 36 floats: stride ≡ 4 (mod 32) -> conflict-free frag loads

__global__ __launch_bounds__(256, 1)
void snn_gemm_tf32(const float* __restrict__ A,
                   const float* __restrict__ W,
                   float* __restrict__ H)
{
    __shared__ float As[GBM][KSTR];
    __shared__ float Bs[GBN][KSTR];

    const int tid  = threadIdx.x;
    const int lane = tid & 31;
    const int wid  = tid >> 5;
    const int wm   = wid & 3;        // warp row 0..3  (32 rows each)
    const int wn   = wid >> 2;       // warp col 0..1  (64 cols each)
    const int g    = lane >> 2;      // 0..7
    const int t4   = lane & 3;       // 0..3

    const int bm = blockIdx.x * GBM;
    const int bn = blockIdx.y * GBN;

    // global->smem mapping: each thread 4 float4 rows-of-32 for A and B
    const int lrow = tid >> 3;          // 0..31
    const int lcol = (tid & 7) * 4;     // 0..28

    const float* Ab = A + (size_t)bm * SNN_I;
    const float* Wb = W + (size_t)bn * SNN_I;

    float4 pa[4], pb[4];
    #pragma unroll
    for (int r = 0; r < 4; r++) {
        pa[r] = *(const float4*)(Ab + (size_t)(lrow + 32 * r) * SNN_I + lcol);
        pb[r] = *(const float4*)(Wb + (size_t)(lrow + 32 * r) * SNN_I + lcol);
    }

    float c[2][8][4];
    #pragma unroll
    for (int mt = 0; mt < 2; mt++)
        #pragma unroll
        for (int nt = 0; nt < 8; nt++)
            #pragma unroll
            for (int q = 0; q < 4; q++)
                c[mt][nt][q] = 0.0f;

    #pragma unroll 1
    for (int kt = 0; kt < SNN_I / GBK; kt++) {
        // store prefetched tile (converted to TF32 bit patterns)
        #pragma unroll
        for (int r = 0; r < 4; r++) {
            float* as = &As[lrow + 32 * r][lcol];
            as[0] = __uint_as_float(f2tf32(pa[r].x));
            as[1] = __uint_as_float(f2tf32(pa[r].y));
            as[2] = __uint_as_float(f2tf32(pa[r].z));
            as[3] = __uint_as_float(f2tf32(pa[r].w));
            float* bs = &Bs[lrow + 32 * r][lcol];
            bs[0] = __uint_as_float(f2tf32(pb[r].x));
            bs[1] = __uint_as_float(f2tf32(pb[r].y));
            bs[2] = __uint_as_float(f2tf32(pb[r].z));
            bs[3] = __uint_as_float(f2tf32(pb[r].w));
        }
        __syncthreads();

        // kick off next tile's global loads early (hide DRAM latency in compute)
        if (kt + 1 < SNN_I / GBK) {
            const int koff = (kt + 1) * GBK + lcol;
            #pragma unroll
            for (int r = 0; r < 4; r++) {
                pa[r] = *(const float4*)(Ab + (size_t)(lrow + 32 * r) * SNN_I + koff);
                pb[r] = *(const float4*)(Wb + (size_t)(lrow + 32 * r) * SNN_I + koff);
            }
        }

        // compute: 4 k-steps of 8
        #pragma unroll
        for (int kk = 0; kk < GBK; kk += 8) {
            uint32_t a[2][4], b[8][2];
            #pragma unroll
            for (int mt = 0; mt < 2; mt++) {
                const int row = wm * 32 + mt * 16 + g;
                a[mt][0] = __float_as_uint(As[row    ][kk + t4    ]);
                a[mt][1] = __float_as_uint(As[row + 8][kk + t4    ]);
                a[mt][2] = __float_as_uint(As[row    ][kk + t4 + 4]);
                a[mt][3] = __float_as_uint(As[row + 8][kk + t4 + 4]);
            }
            #pragma unroll
            for (int nt = 0; nt < 8; nt++) {
                const int col = wn * 64 + nt * 8 + g;
                b[nt][0] = __float_as_uint(Bs[col][kk + t4    ]);
                b[nt][1] = __float_as_uint(Bs[col][kk + t4 + 4]);
            }
            #pragma unroll
            for (int mt = 0; mt < 2; mt++)
                #pragma unroll
                for (int nt = 0; nt < 8; nt++) {
                    asm volatile(
                        "mma.sync.aligned.m16n8k8.row.col.f32.tf32.tf32.f32 "
                        "{%0,%1,%2,%3}, {%4,%5,%6,%7}, {%8,%9}, {%0,%1,%2,%3};"
                        : "+f"(c[mt][nt][0]), "+f"(c[mt][nt][1]),
                          "+f"(c[mt][nt][2]), "+f"(c[mt][nt][3])
                        : "r"(a[mt][0]), "r"(a[mt][1]), "r"(a[mt][2]), "r"(a[mt][3]),
                          "r"(b[nt][0]), "r"(b[nt][1]));
                }
        }
        __syncthreads();
    }

    // epilogue: D[g][2*t4], D[g][2*t4+1], D[g+8][2*t4], D[g+8][2*t4+1]
    #pragma unroll
    for (int mt = 0; mt < 2; mt++) {
        #pragma unroll
        for (int nt = 0; nt < 8; nt++) {
            const int row = bm + wm * 32 + mt * 16 + g;
            const int col = bn + wn * 64 + nt * 8 + t4 * 2;
            float2 v0 = {c[mt][nt][0], c[mt][nt][1]};
            float2 v1 = {c[mt][nt][2], c[mt][nt][3]};
            *(float2*)(H + (size_t)row * SNN_O + col)       = v0;
            *(float2*)(H + (size_t)(row + 8) * SNN_O + col) = v1;
        }
    }
}

// ---------------------------------------------------------------------------
// Scan phase 1: each (chain, chunk) does a local scan from zero state,
// stores the chunk-final (flt, out).
// Thread mapping: idx = ((b*CHUNKS + c) << 8) | o  -> o fastest = coalesced.
// ---------------------------------------------------------------------------
__global__ __launch_bounds__(256)
void snn_scan_phase1(const float* __restrict__ H)
{
    const int idx  = blockIdx.x * blockDim.x + threadIdx.x;  // 0..131071
    const int o    = idx & 255;
    const int rest = idx >> 8;         // 0..511
    const int cidx = rest & (CHUNKS - 1);
    const int b    = rest >> 3;

    const float* hp = H + ((size_t)b * SNN_T + cidx * CHUNK_L) * SNN_O + o;

    float flt = 0.0f, out = 0.0f;
    #pragma unroll 1
    for (int t = 0; t < CHUNK_L; t += 5) {
        float v[5];
        #pragma unroll
        for (int j = 0; j < 5; j++)
            v[j] = __ldg(hp + (size_t)(t + j) * SNN_O);
        #pragma unroll
        for (int j = 0; j < 5; j++) {
            float nf = fmaf(ALPHA, flt, v[j]);
            out = fmaf(BETA, out, flt);
            flt = nf;
        }
    }
    g_end[idx] = make_float2(flt, out);
}

// ---------------------------------------------------------------------------
// Scan phase 2: per chain, serially combine chunk states.
//   s_init[c+1] = M^L * s_init[c] + s_end_local[c],  M^L = [[aL,0],[cL,bL]]
// ---------------------------------------------------------------------------
__global__ __launch_bounds__(256)
void snn_scan_phase2()
{
    const int idx = blockIdx.x * blockDim.x + threadIdx.x;   // 0..16383
    const int o = idx & 255;
    const int b = idx >> 8;

    // M^L powers, computed in fp64 (cheap, exact enough)
    double ad = 1.0, bd = 1.0;
    for (int i = 0; i < CHUNK_L; i++) { ad *= (double)ALPHA; bd *= (double)BETA; }
    const float aL = (float)ad;
    const float bL = (float)bd;
    const float cL = (float)((ad - bd) / ((double)ALPHA - (double)BETA));

    float fi = 0.0f, oi = 0.0f;
    #pragma unroll
    for (int cidx = 0; cidx < CHUNKS; cidx++) {
        const int sidx = ((b * CHUNKS + cidx) << 8) | o;
        g_init[sidx] = make_float2(fi, oi);
        float2 e = g_end[sidx];
        float fn = fmaf(aL, fi, e.x);
        float on = fmaf(bL, oi, fmaf(cL, fi, e.y));
        fi = fn; oi = on;
    }
}

// ---------------------------------------------------------------------------
// Scan phase 3: rescan each chunk from its exact initial state; write output.
// ---------------------------------------------------------------------------
__global__ __launch_bounds__(256)
void snn_scan_phase3(const float* __restrict__ H, float* __restrict__ out)
{
    const int idx  = blockIdx.x * blockDim.x + threadIdx.x;
    const int o    = idx & 255;
    const int rest = idx >> 8;
    const int cidx = rest & (CHUNKS - 1);
    const int b    = rest >> 3;

    const size_t base = ((size_t)b * SNN_T + cidx * CHUNK_L) * SNN_O + o;
    const float* hp = H + base;
    float*       op = out + base;

    float2 s = g_init[idx];
    float flt = s.x, acc = s.y;

    #pragma unroll 1
    for (int t = 0; t < CHUNK_L; t += 5) {
        float v[5];
        #pragma unroll
        for (int j = 0; j < 5; j++)
            v[j] = __ldg(hp + (size_t)(t + j) * SNN_O);
        #pragma unroll
        for (int j = 0; j < 5; j++) {
            float nf = fmaf(ALPHA, flt, v[j]);
            acc = fmaf(BETA, acc, flt);      // uses OLD flt
            flt = nf;
            op[(size_t)(t + j) * SNN_O] = acc;
        }
    }
}

// ---------------------------------------------------------------------------
// Launch
// ---------------------------------------------------------------------------
extern "C" void kernel_launch(void* const* d_in, const int* in_sizes, int n_in,
                              void* d_out, int out_size)
{
    const float* inputs = (const float*)d_in[0];   // (B, T, I)
    const float* W      = (const float*)d_in[1];   // (O, I)
    float* out = (float*)d_out;                    // (B, T, O)

    float* h;
    cudaGetSymbolAddress((void**)&h, g_h);

    dim3 gemm_grid(SNN_B * SNN_T / GBM, SNN_O / GBN);  // (500, 2)
    snn_gemm_tf32<<<gemm_grid, 256>>>(inputs, W, h);

    const int pthreads = CHAINS * CHUNKS;              // 131072
    snn_scan_phase1<<<pthreads / 256, 256>>>(h);
    snn_scan_phase2<<<CHAINS / 256, 256>>>();
    snn_scan_phase3<<<pthreads / 256, 256>>>(h, out);
}

// round 4
// speedup vs baseline: 2.6926x; 1.0263x over previous
#include <cuda_runtime.h>
#include <cuda_bf16.h>
#include <cstdint>

// Problem shape (fixed): B=64, T=1000, I=512, O=256
#define SNN_B 64
#define SNN_T 1000
#define SNN_I 512
#define SNN_O 256
#define ALPHA 0.95f
#define BETA  0.9f

#define CHUNKS 8
#define CHUNK_L 125
#define CHAINS (SNN_B * SNN_O)   // 16384

__device__ float  g_h[(size_t)SNN_B * SNN_T * SNN_O];
__device__ float2 g_end [CHAINS * CHUNKS];
__device__ float2 g_init[CHAINS * CHUNKS];

__device__ __forceinline__ uint32_t f2tf32(float x) {
    uint32_t r;
    asm("cvt.rna.tf32.f32 %0, %1;" : "=r"(r) : "f"(x));
    return r;
}

// ---------------------------------------------------------------------------
// Kernel 1: TF32 tensor-core GEMM, permuted smem for vectorized frag loads.
//   Block 128x128x32, 256 threads (8 warps 4x2), warp tile 32x64.
//   smem layout: As[m][k'] with k' = (k&3)*8 + (k>>2)  (k = tile-local 0..31)
//   => thread t4's fragment k-values (k ≡ t4 mod 4) are contiguous in k'.
// ---------------------------------------------------------------------------
#define GBM 128
#define GBN 128
#define GBK 32
#define KS  36   // stride pad: float4-aligned, 2-way conflicts max

__global__ __launch_bounds__(256, 1)
void snn_gemm_tf32(const float* __restrict__ A,
                   const float* __restrict__ W,
                   float* __restrict__ H)
{
    __shared__ float As[GBM][KS];
    __shared__ float Bs[GBN][KS];

    const int tid  = threadIdx.x;
    const int lane = tid & 31;
    const int wid  = tid >> 5;
    const int wm   = wid & 3;        // warp row (32 rows)
    const int wn   = wid >> 2;       // warp col (64 cols)
    const int g    = lane >> 2;      // 0..7
    const int t4   = lane & 3;       // 0..3

    const int bm = blockIdx.x * GBM;
    const int bn = blockIdx.y * GBN;

    // global->smem: each thread loads 4 float4 of A and of W per K-tile
    const int lrow = tid >> 3;          // 0..31
    const int lcol = (tid & 7) * 4;     // 0,4,..,28 (consecutive k)
    const int kq   = tid & 7;           // k>>2 for this thread's float4

    const float* Ab = A + (size_t)bm * SNN_I;
    const float* Wb = W + (size_t)bn * SNN_I;

    float4 pa[4], pb[4];
    #pragma unroll
    for (int r = 0; r < 4; r++) {
        pa[r] = *(const float4*)(Ab + (size_t)(lrow + 32 * r) * SNN_I + lcol);
        pb[r] = *(const float4*)(Wb + (size_t)(lrow + 32 * r) * SNN_I + lcol);
    }

    float c[2][8][4];
    #pragma unroll
    for (int mt = 0; mt < 2; mt++)
        #pragma unroll
        for (int nt = 0; nt < 8; nt++)
            #pragma unroll
            for (int q = 0; q < 4; q++)
                c[mt][nt][q] = 0.0f;

    #pragma unroll 1
    for (int kt = 0; kt < SNN_I / GBK; kt++) {
        // store with permutation: k = lcol + j  ->  k' = j*8 + kq
        #pragma unroll
        for (int r = 0; r < 4; r++) {
            const int row = lrow + 32 * r;
            As[row][0 * 8 + kq] = __uint_as_float(f2tf32(pa[r].x));
            As[row][1 * 8 + kq] = __uint_as_float(f2tf32(pa[r].y));
            As[row][2 * 8 + kq] = __uint_as_float(f2tf32(pa[r].z));
            As[row][3 * 8 + kq] = __uint_as_float(f2tf32(pa[r].w));
            Bs[row][0 * 8 + kq] = __uint_as_float(f2tf32(pb[r].x));
            Bs[row][1 * 8 + kq] = __uint_as_float(f2tf32(pb[r].y));
            Bs[row][2 * 8 + kq] = __uint_as_float(f2tf32(pb[r].z));
            Bs[row][3 * 8 + kq] = __uint_as_float(f2tf32(pb[r].w));
        }
        __syncthreads();

        // prefetch next K-tile
        if (kt + 1 < SNN_I / GBK) {
            const int koff = (kt + 1) * GBK + lcol;
            #pragma unroll
            for (int r = 0; r < 4; r++) {
                pa[r] = *(const float4*)(Ab + (size_t)(lrow + 32 * r) * SNN_I + koff);
                pb[r] = *(const float4*)(Wb + (size_t)(lrow + 32 * r) * SNN_I + koff);
            }
        }

        // two halves; each half = one float4 per row/col = 2 kk-steps (s)
        #pragma unroll
        for (int half = 0; half < 2; half++) {
            const int kb = t4 * 8 + half * 4;
            float4 afr[2][2];
            #pragma unroll
            for (int mt = 0; mt < 2; mt++) {
                const int row = wm * 32 + mt * 16 + g;
                afr[mt][0] = *(const float4*)&As[row    ][kb];
                afr[mt][1] = *(const float4*)&As[row + 8][kb];
            }
            float4 bfr[8];
            #pragma unroll
            for (int nt = 0; nt < 8; nt++) {
                const int col = wn * 64 + nt * 8 + g;
                bfr[nt] = *(const float4*)&Bs[col][kb];
            }
            #pragma unroll
            for (int ss = 0; ss < 2; ss++) {
                #pragma unroll
                for (int mt = 0; mt < 2; mt++) {
                    const float* f0 = (const float*)&afr[mt][0];
                    const float* f1 = (const float*)&afr[mt][1];
                    uint32_t a0 = __float_as_uint(f0[2 * ss]);
                    uint32_t a1 = __float_as_uint(f1[2 * ss]);
                    uint32_t a2 = __float_as_uint(f0[2 * ss + 1]);
                    uint32_t a3 = __float_as_uint(f1[2 * ss + 1]);
                    #pragma unroll
                    for (int nt = 0; nt < 8; nt++) {
                        const float* fb = (const float*)&bfr[nt];
                        uint32_t b0 = __float_as_uint(fb[2 * ss]);
                        uint32_t b1 = __float_as_uint(fb[2 * ss + 1]);
                        asm volatile(
                            "mma.sync.aligned.m16n8k8.row.col.f32.tf32.tf32.f32 "
                            "{%0,%1,%2,%3}, {%4,%5,%6,%7}, {%8,%9}, {%0,%1,%2,%3};"
                            : "+f"(c[mt][nt][0]), "+f"(c[mt][nt][1]),
                              "+f"(c[mt][nt][2]), "+f"(c[mt][nt][3])
                            : "r"(a0), "r"(a1), "r"(a2), "r"(a3),
                              "r"(b0), "r"(b1));
                    }
                }
            }
        }
        __syncthreads();
    }

    #pragma unroll
    for (int mt = 0; mt < 2; mt++) {
        #pragma unroll
        for (int nt = 0; nt < 8; nt++) {
            const int row = bm + wm * 32 + mt * 16 + g;
            const int col = bn + wn * 64 + nt * 8 + t4 * 2;
            float2 v0 = {c[mt][nt][0], c[mt][nt][1]};
            float2 v1 = {c[mt][nt][2], c[mt][nt][3]};
            *(float2*)(H + (size_t)row * SNN_O + col)       = v0;
            *(float2*)(H + (size_t)(row + 8) * SNN_O + col) = v1;
        }
    }
}

// ---------------------------------------------------------------------------
// Scan phase 1: local scan per (chain-pair, chunk), float2 over o.
// ---------------------------------------------------------------------------
__global__ __launch_bounds__(256)
void snn_scan_phase1(const float* __restrict__ H)
{
    const int idx  = blockIdx.x * blockDim.x + threadIdx.x;  // 0..65535
    const int o2   = idx & 127;
    const int rest = idx >> 7;
    const int cidx = rest & (CHUNKS - 1);
    const int b    = rest >> 3;

    const float2* hp = (const float2*)(H + ((size_t)b * SNN_T + cidx * CHUNK_L) * SNN_O) + o2;

    float2 flt = {0.f, 0.f}, out = {0.f, 0.f};
    #pragma unroll 1
    for (int t = 0; t < CHUNK_L; t += 5) {
        float2 v[5];
        #pragma unroll
        for (int j = 0; j < 5; j++)
            v[j] = __ldg(hp + (size_t)(t + j) * (SNN_O / 2));
        #pragma unroll
        for (int j = 0; j < 5; j++) {
            float nx = fmaf(ALPHA, flt.x, v[j].x);
            float ny = fmaf(ALPHA, flt.y, v[j].y);
            out.x = fmaf(BETA, out.x, flt.x);
            out.y = fmaf(BETA, out.y, flt.y);
            flt.x = nx; flt.y = ny;
        }
    }
    const int base = ((b * CHUNKS + cidx) << 8) | (o2 * 2);
    g_end[base]     = make_float2(flt.x, out.x);
    g_end[base + 1] = make_float2(flt.y, out.y);
}

// ---------------------------------------------------------------------------
// Scan phase 2: serial combine of chunk states per chain.
// ---------------------------------------------------------------------------
__global__ __launch_bounds__(256)
void snn_scan_phase2()
{
    const int idx = blockIdx.x * blockDim.x + threadIdx.x;   // 0..16383
    const int o = idx & 255;
    const int b = idx >> 8;

    double ad = 1.0, bd = 1.0;
    for (int i = 0; i < CHUNK_L; i++) { ad *= (double)ALPHA; bd *= (double)BETA; }
    const float aL = (float)ad;
    const float bL = (float)bd;
    const float cL = (float)((ad - bd) / ((double)ALPHA - (double)BETA));

    float fi = 0.0f, oi = 0.0f;
    #pragma unroll
    for (int cidx = 0; cidx < CHUNKS; cidx++) {
        const int sidx = ((b * CHUNKS + cidx) << 8) | o;
        g_init[sidx] = make_float2(fi, oi);
        float2 e = g_end[sidx];
        float fn = fmaf(aL, fi, e.x);
        float on = fmaf(bL, oi, fmaf(cL, fi, e.y));
        fi = fn; oi = on;
    }
}

// ---------------------------------------------------------------------------
// Scan phase 3: rescan from exact init state, write output (float2 over o).
// ---------------------------------------------------------------------------
__global__ __launch_bounds__(256)
void snn_scan_phase3(const float* __restrict__ H, float* __restrict__ out)
{
    const int idx  = blockIdx.x * blockDim.x + threadIdx.x;  // 0..65535
    const int o2   = idx & 127;
    const int rest = idx >> 7;
    const int cidx = rest & (CHUNKS - 1);
    const int b    = rest >> 3;

    const size_t base = ((size_t)b * SNN_T + cidx * CHUNK_L) * SNN_O;
    const float2* hp = (const float2*)(H + base) + o2;
    float2*       op = (float2*)(out + base) + o2;

    const int sbase = ((b * CHUNKS + cidx) << 8) | (o2 * 2);
    float2 s0 = g_init[sbase];
    float2 s1 = g_init[sbase + 1];
    float2 flt = {s0.x, s1.x};
    float2 acc = {s0.y, s1.y};

    #pragma unroll 1
    for (int t = 0; t < CHUNK_L; t += 5) {
        float2 v[5];
        #pragma unroll
        for (int j = 0; j < 5; j++)
            v[j] = __ldg(hp + (size_t)(t + j) * (SNN_O / 2));
        #pragma unroll
        for (int j = 0; j < 5; j++) {
            float nx = fmaf(ALPHA, flt.x, v[j].x);
            float ny = fmaf(ALPHA, flt.y, v[j].y);
            acc.x = fmaf(BETA, acc.x, flt.x);
            acc.y = fmaf(BETA, acc.y, flt.y);
            flt.x = nx; flt.y = ny;
            op[(size_t)(t + j) * (SNN_O / 2)] = acc;
        }
    }
}

// ---------------------------------------------------------------------------
// Launch
// ---------------------------------------------------------------------------
extern "C" void kernel_launch(void* const* d_in, const int* in_sizes, int n_in,
                              void* d_out, int out_size)
{
    const float* inputs = (const float*)d_in[0];   // (B, T, I)
    const float* W      = (const float*)d_in[1];   // (O, I)
    float* out = (float*)d_out;                    // (B, T, O)

    float* h;
    cudaGetSymbolAddress((void**)&h, g_h);

    dim3 gemm_grid(SNN_B * SNN_T / GBM, SNN_O / GBN);  // (500, 2)
    snn_gemm_tf32<<<gemm_grid, 256>>>(inputs, W, h);

    const int p2threads = CHAINS * CHUNKS / 2;          // 65536
    snn_scan_phase1<<<p2threads / 256, 256>>>(h);
    snn_scan_phase2<<<CHAINS / 256, 256>>>();
    snn_scan_phase3<<<p2threads / 256, 256>>>(h, out);
}

// round 6
// speedup vs baseline: 2.7823x; 1.0333x over previous
#include <cuda_runtime.h>
#include <cuda_fp16.h>
#include <cstdint>

// Problem shape (fixed): B=64, T=1000, I=512, O=256
#define SNN_B 64
#define SNN_T 1000
#define SNN_I 512
#define SNN_O 256
#define ALPHA 0.95f
#define BETA  0.9f

#define CHUNKS 10
#define CHUNK_L 100
#define CHAINS (SNN_B * SNN_O)   // 16384

// H scratch now fp16: 32.7 MB
__device__ __half  g_h[(size_t)SNN_B * SNN_T * SNN_O];
__device__ float2  g_end [CHAINS * CHUNKS];
__device__ float2  g_init[CHAINS * CHUNKS];

__device__ __forceinline__ uint32_t smem_u32(const void* p) {
    uint32_t a;
    asm("{ .reg .u64 t; cvta.to.shared.u64 t, %1; cvt.u32.u64 %0, t; }" : "=r"(a) : "l"(p));
    return a;
}

// ===========================================================================
// Kernel 1: FP16 tensor-core GEMM  H[m][n] = (half) sum_k A[m][k] * W[n][k]
//   Block tile 128x128, BK=32 halves (64B smem rows), 256 threads (8 warps 4x2),
//   warp tile 32x64. mma.sync.m16n8k16.f32.f16.f16.f32, ldmatrix.x4 frags.
//   Smem swizzle: 64B rows, 16B seg index ^= (row>>1)&3  (conflict-free).
// ===========================================================================
#define GBM 128
#define GBN 128
#define BKH 32    // k halves per tile

__global__ __launch_bounds__(256, 1)
void snn_gemm_f16(const float* __restrict__ A,
                  const float* __restrict__ W,
                  __half* __restrict__ H)
{
    __shared__ __align__(16) __half Asm[GBM * BKH];   // 8 KB
    __shared__ __align__(16) __half Bsm[GBN * BKH];   // 8 KB

    const int tid  = threadIdx.x;
    const int lane = tid & 31;
    const int wid  = tid >> 5;
    const int wm   = wid & 3;       // 32-row band
    const int wn   = wid >> 2;      // 64-col band
    const int g    = lane >> 2;
    const int t4   = lane & 3;

    const int bm = blockIdx.x * GBM;
    const int bn = blockIdx.y * GBN;

    // loader mapping: row = tid>>1 (0..127), 16 floats starting at (tid&1)*16
    const int lrow = tid >> 1;
    const int lc0  = (tid & 1) * 16;
    const float* Ap = A + (size_t)(bm + lrow) * SNN_I + lc0;
    const float* Wp = W + (size_t)(bn + lrow) * SNN_I + lc0;

    const uint32_t sA = smem_u32(Asm);
    const uint32_t sB = smem_u32(Bsm);
    const int xrow = (lrow >> 1) & 3;   // swizzle key for the loader's row

    float4 pa[4], pb[4];
    #pragma unroll
    for (int j = 0; j < 4; j++) {
        pa[j] = *(const float4*)(Ap + j * 4);
        pb[j] = *(const float4*)(Wp + j * 4);
    }

    float c[2][8][4];
    #pragma unroll
    for (int mt = 0; mt < 2; mt++)
        #pragma unroll
        for (int nt = 0; nt < 8; nt++)
            #pragma unroll
            for (int q = 0; q < 4; q++)
                c[mt][nt][q] = 0.0f;

    #pragma unroll 1
    for (int kt = 0; kt < SNN_I / BKH; kt++) {
        // store prefetched tile as half with swizzle
        #pragma unroll
        for (int j = 0; j < 4; j++) {
            const int colb = (lc0 + j * 4) * 2;            // byte offset in 64B row
            const int seg  = colb >> 4;
            const int rem  = colb & 15;                    // 0 or 8
            const uint32_t off = lrow * 64 + (((seg ^ xrow) << 4) | rem);
            __half2 a0 = __floats2half2_rn(pa[j].x, pa[j].y);
            __half2 a1 = __floats2half2_rn(pa[j].z, pa[j].w);
            __half2 b0 = __floats2half2_rn(pb[j].x, pb[j].y);
            __half2 b1 = __floats2half2_rn(pb[j].z, pb[j].w);
            uint2 av = {*(uint32_t*)&a0, *(uint32_t*)&a1};
            uint2 bv = {*(uint32_t*)&b0, *(uint32_t*)&b1};
            *(uint2*)((char*)Asm + off) = av;
            *(uint2*)((char*)Bsm + off) = bv;
        }
        __syncthreads();

        if (kt + 1 < SNN_I / BKH) {
            const float* Apn = Ap + (kt + 1) * BKH;
            const float* Wpn = Wp + (kt + 1) * BKH;
            #pragma unroll
            for (int j = 0; j < 4; j++) {
                pa[j] = *(const float4*)(Apn + j * 4);
                pb[j] = *(const float4*)(Wpn + j * 4);
            }
        }

        // two k16 steps per tile
        #pragma unroll
        for (int s = 0; s < 2; s++) {
            uint32_t af[2][4];
            #pragma unroll
            for (int mt = 0; mt < 2; mt++) {
                const int row = wm * 32 + mt * 16 + (lane & 15);
                const int seg = s * 2 + (lane >> 4);
                const uint32_t addr = sA + row * 64 + ((seg ^ ((row >> 1) & 3)) << 4);
                asm volatile(
                    "ldmatrix.sync.aligned.m8n8.x4.shared.b16 {%0,%1,%2,%3}, [%4];"
                    : "=r"(af[mt][0]), "=r"(af[mt][1]), "=r"(af[mt][2]), "=r"(af[mt][3])
                    : "r"(addr));
            }
            uint32_t bf[4][4];
            #pragma unroll
            for (int p = 0; p < 4; p++) {
                const int row = wn * 64 + p * 16 + (lane & 15);
                const int seg = s * 2 + (lane >> 4);
                const uint32_t addr = sB + row * 64 + ((seg ^ ((row >> 1) & 3)) << 4);
                asm volatile(
                    "ldmatrix.sync.aligned.m8n8.x4.shared.b16 {%0,%1,%2,%3}, [%4];"
                    : "=r"(bf[p][0]), "=r"(bf[p][1]), "=r"(bf[p][2]), "=r"(bf[p][3])
                    : "r"(addr));
            }
            #pragma unroll
            for (int mt = 0; mt < 2; mt++)
                #pragma unroll
                for (int nt = 0; nt < 8; nt++) {
                    const int p = nt >> 1, hi = nt & 1;
                    asm volatile(
                        "mma.sync.aligned.m16n8k16.row.col.f32.f16.f16.f32 "
                        "{%0,%1,%2,%3}, {%4,%5,%6,%7}, {%8,%9}, {%0,%1,%2,%3};"
                        : "+f"(c[mt][nt][0]), "+f"(c[mt][nt][1]),
                          "+f"(c[mt][nt][2]), "+f"(c[mt][nt][3])
                        : "r"(af[mt][0]), "r"(af[mt][1]), "r"(af[mt][2]), "r"(af[mt][3]),
                          "r"(bf[p][hi]), "r"(bf[p][hi + 2]));
                }
        }
        __syncthreads();
    }

    // epilogue: half2 stores
    #pragma unroll
    for (int mt = 0; mt < 2; mt++) {
        #pragma unroll
        for (int nt = 0; nt < 8; nt++) {
            const int row = bm + wm * 32 + mt * 16 + g;
            const int col = bn + wn * 64 + nt * 8 + t4 * 2;
            __half2 v0 = __floats2half2_rn(c[mt][nt][0], c[mt][nt][1]);
            __half2 v1 = __floats2half2_rn(c[mt][nt][2], c[mt][nt][3]);
            *(__half2*)(H + (size_t)row * SNN_O + col)       = v0;
            *(__half2*)(H + (size_t)(row + 8) * SNN_O + col) = v1;
        }
    }
}

// ===========================================================================
// Scan: 3-phase chunk-parallel; H is fp16, 4 chains per thread.
// ===========================================================================
__global__ __launch_bounds__(256)
void snn_scan_phase1(const __half* __restrict__ H)
{
    const int idx  = blockIdx.x * blockDim.x + threadIdx.x;  // 0..40959
    const int o4   = idx & 63;
    const int rest = idx >> 6;
    const int cidx = rest % CHUNKS;
    const int b    = rest / CHUNKS;

    const char* hp = (const char*)(H + ((size_t)b * SNN_T + cidx * CHUNK_L) * SNN_O + o4 * 4);

    float f[4] = {0, 0, 0, 0}, o[4] = {0, 0, 0, 0};
    #pragma unroll 1
    for (int t = 0; t < CHUNK_L; t += 4) {
        uint2 v[4];
        #pragma unroll
        for (int j = 0; j < 4; j++)
            v[j] = *(const uint2*)(hp + (size_t)(t + j) * (SNN_O * 2));
        #pragma unroll
        for (int j = 0; j < 4; j++) {
            __half2 lo = *(__half2*)&v[j].x;
            __half2 hi = *(__half2*)&v[j].y;
            float h0 = __low2float(lo), h1 = __high2float(lo);
            float h2 = __low2float(hi), h3 = __high2float(hi);
            float n0 = fmaf(ALPHA, f[0], h0), n1 = fmaf(ALPHA, f[1], h1);
            float n2 = fmaf(ALPHA, f[2], h2), n3 = fmaf(ALPHA, f[3], h3);
            o[0] = fmaf(BETA, o[0], f[0]); o[1] = fmaf(BETA, o[1], f[1]);
            o[2] = fmaf(BETA, o[2], f[2]); o[3] = fmaf(BETA, o[3], f[3]);
            f[0] = n0; f[1] = n1; f[2] = n2; f[3] = n3;
        }
    }
    const int sbase = ((b * CHUNKS + cidx) << 8) | (o4 * 4);
    #pragma unroll
    for (int q = 0; q < 4; q++)
        g_end[sbase + q] = make_float2(f[q], o[q]);
}

__global__ __launch_bounds__(256)
void snn_scan_phase2()
{
    const int idx = blockIdx.x * blockDim.x + threadIdx.x;   // 0..16383
    const int o = idx & 255;
    const int b = idx >> 8;

    double ad = 1.0, bd = 1.0;
    for (int i = 0; i < CHUNK_L; i++) { ad *= (double)ALPHA; bd *= (double)BETA; }
    const float aL = (float)ad;
    const float bL = (float)bd;
    const float cL = (float)((ad - bd) / ((double)ALPHA - (double)BETA));

    float fi = 0.0f, oi = 0.0f;
    #pragma unroll
    for (int cidx = 0; cidx < CHUNKS; cidx++) {
        const int sidx = ((b * CHUNKS + cidx) << 8) | o;
        g_init[sidx] = make_float2(fi, oi);
        float2 e = g_end[sidx];
        float fn = fmaf(aL, fi, e.x);
        float on = fmaf(bL, oi, fmaf(cL, fi, e.y));
        fi = fn; oi = on;
    }
}

__global__ __launch_bounds__(256)
void snn_scan_phase3(const __half* __restrict__ H, float* __restrict__ out)
{
    const int idx  = blockIdx.x * blockDim.x + threadIdx.x;
    const int o4   = idx & 63;
    const int rest = idx >> 6;
    const int cidx = rest % CHUNKS;
    const int b    = rest / CHUNKS;

    const size_t ebase = ((size_t)b * SNN_T + cidx * CHUNK_L) * SNN_O + o4 * 4;
    const char* hp = (const char*)(H + ebase);
    float*      op = out + ebase;

    const int sbase = ((b * CHUNKS + cidx) << 8) | (o4 * 4);
    float f[4], o[4];
    #pragma unroll
    for (int q = 0; q < 4; q++) {
        float2 s = g_init[sbase + q];
        f[q] = s.x; o[q] = s.y;
    }

    #pragma unroll 1
    for (int t = 0; t < CHUNK_L; t += 4) {
        uint2 v[4];
        #pragma unroll
        for (int j = 0; j < 4; j++)
            v[j] = *(const uint2*)(hp + (size_t)(t + j) * (SNN_O * 2));
        #pragma unroll
        for (int j = 0; j < 4; j++) {
            __half2 lo = *(__half2*)&v[j].x;
            __half2 hi = *(__half2*)&v[j].y;
            float h0 = __low2float(lo), h1 = __high2float(lo);
            float h2 = __low2float(hi), h3 = __high2float(hi);
            float n0 = fmaf(ALPHA, f[0], h0), n1 = fmaf(ALPHA, f[1], h1);
            float n2 = fmaf(ALPHA, f[2], h2), n3 = fmaf(ALPHA, f[3], h3);
            o[0] = fmaf(BETA, o[0], f[0]); o[1] = fmaf(BETA, o[1], f[1]);
            o[2] = fmaf(BETA, o[2], f[2]); o[3] = fmaf(BETA, o[3], f[3]);
            f[0] = n0; f[1] = n1; f[2] = n2; f[3] = n3;
            float4 w = {o[0], o[1], o[2], o[3]};
            *(float4*)(op + (size_t)(t + j) * SNN_O) = w;
        }
    }
}

// ---------------------------------------------------------------------------
extern "C" void kernel_launch(void* const* d_in, const int* in_sizes, int n_in,
                              void* d_out, int out_size)
{
    const float* inputs = (const float*)d_in[0];   // (B, T, I)
    const float* W      = (const float*)d_in[1];   // (O, I)
    float* out = (float*)d_out;                    // (B, T, O) fp32

    __half* h;
    cudaGetSymbolAddress((void**)&h, g_h);

    dim3 gemm_grid(SNN_B * SNN_T / GBM, SNN_O / GBN);  // (500, 2)
    snn_gemm_f16<<<gemm_grid, 256>>>(inputs, W, h);

    const int pthreads = SNN_B * CHUNKS * (SNN_O / 4);   // 40960
    snn_scan_phase1<<<pthreads / 256, 256>>>(h);
    snn_scan_phase2<<<CHAINS / 256, 256>>>();
    snn_scan_phase3<<<pthreads / 256, 256>>>(h, out);
}

// round 8
// speedup vs baseline: 2.8225x; 1.0145x over previous
#include <cuda_runtime.h>
#include <cuda_fp16.h>
#include <cstdint>

// Problem shape (fixed): B=64, T=1000, I=512, O=256
#define SNN_B 64
#define SNN_T 1000
#define SNN_I 512
#define SNN_O 256
#define ALPHA 0.95f
#define BETA  0.9f

#define CHUNKS 8
#define CHUNK_L 125              // == GEMM M-tile; 8 * 125 = 1000
#define CHAINS (SNN_B * SNN_O)   // 16384
#define MROWS (SNN_B * SNN_T)    // 64000

// H scratch fp16 (32.7 MB) + chunk-end states
__device__ __half  g_h[(size_t)MROWS * SNN_O];
__device__ float2  g_end[CHAINS * CHUNKS];

__device__ __forceinline__ uint32_t smem_u32(const void* p) {
    uint32_t a;
    asm("{ .reg .u64 t; cvta.to.shared.u64 t, %1; cvt.u32.u64 %0, t; }" : "=r"(a) : "l"(p));
    return a;
}

// ===========================================================================
// Kernel 1: FP16 MMA GEMM (M-tile = 125 rows = one scan chunk) with fused
// local chunk-scan epilogue (produces g_end, replacing scan phase 1).
//   Block tile 125(pad 128) x 128, BK=32 halves, 256 threads (8 warps 4x2).
// ===========================================================================
#define GBN 128
#define BKH 32
#define MTILE 125

__global__ __launch_bounds__(256, 1)
void snn_gemm_f16(const float* __restrict__ A,
                  const float* __restrict__ W,
                  __half* __restrict__ H)
{
    __shared__ __align__(16) __half Asm[128 * BKH];     // 8 KB
    __shared__ __align__(16) __half Bsm[GBN * BKH];     // 8 KB
    __shared__ __align__(16) __half Hst[MTILE * 128];   // 31.25 KB stage for scan

    const int tid  = threadIdx.x;
    const int lane = tid & 31;
    const int wid  = tid >> 5;
    const int wm   = wid & 3;
    const int wn   = wid >> 2;
    const int g    = lane >> 2;
    const int t4   = lane & 3;

    const int bm = blockIdx.x * MTILE;       // 512 tiles
    const int bn = blockIdx.y * GBN;         // 2 tiles

    // loader: row = tid>>1 (0..127), 16 floats starting at (tid&1)*16
    const int lrow = tid >> 1;
    const int lc0  = (tid & 1) * 16;
    const int arow = min(bm + lrow, MROWS - 1);   // clamp tail-tile overreach
    const float* Ap = A + (size_t)arow * SNN_I + lc0;
    const float* Wp = W + (size_t)(bn + lrow) * SNN_I + lc0;

    const uint32_t sA = smem_u32(Asm);
    const uint32_t sB = smem_u32(Bsm);
    const int xrow = (lrow >> 1) & 3;

    float4 pa[4], pb[4];
    #pragma unroll
    for (int j = 0; j < 4; j++) {
        pa[j] = *(const float4*)(Ap + j * 4);
        pb[j] = *(const float4*)(Wp + j * 4);
    }

    float c[2][8][4];
    #pragma unroll
    for (int mt = 0; mt < 2; mt++)
        #pragma unroll
        for (int nt = 0; nt < 8; nt++)
            #pragma unroll
            for (int q = 0; q < 4; q++)
                c[mt][nt][q] = 0.0f;

    #pragma unroll 1
    for (int kt = 0; kt < SNN_I / BKH; kt++) {
        #pragma unroll
        for (int j = 0; j < 4; j++) {
            const int colb = (lc0 + j * 4) * 2;
            const int seg  = colb >> 4;
            const int rem  = colb & 15;
            const uint32_t off = lrow * 64 + (((seg ^ xrow) << 4) | rem);
            __half2 a0 = __floats2half2_rn(pa[j].x, pa[j].y);
            __half2 a1 = __floats2half2_rn(pa[j].z, pa[j].w);
            __half2 b0 = __floats2half2_rn(pb[j].x, pb[j].y);
            __half2 b1 = __floats2half2_rn(pb[j].z, pb[j].w);
            uint2 av = {*(uint32_t*)&a0, *(uint32_t*)&a1};
            uint2 bv = {*(uint32_t*)&b0, *(uint32_t*)&b1};
            *(uint2*)((char*)Asm + off) = av;
            *(uint2*)((char*)Bsm + off) = bv;
        }
        __syncthreads();

        if (kt + 1 < SNN_I / BKH) {
            const float* Apn = Ap + (kt + 1) * BKH;
            const float* Wpn = Wp + (kt + 1) * BKH;
            #pragma unroll
            for (int j = 0; j < 4; j++) {
                pa[j] = *(const float4*)(Apn + j * 4);
                pb[j] = *(const float4*)(Wpn + j * 4);
            }
        }

        #pragma unroll
        for (int s = 0; s < 2; s++) {
            uint32_t af[2][4];
            #pragma unroll
            for (int mt = 0; mt < 2; mt++) {
                const int row = wm * 32 + mt * 16 + (lane & 15);
                const int seg = s * 2 + (lane >> 4);
                const uint32_t addr = sA + row * 64 + ((seg ^ ((row >> 1) & 3)) << 4);
                asm volatile(
                    "ldmatrix.sync.aligned.m8n8.x4.shared.b16 {%0,%1,%2,%3}, [%4];"
                    : "=r"(af[mt][0]), "=r"(af[mt][1]), "=r"(af[mt][2]), "=r"(af[mt][3])
                    : "r"(addr));
            }
            uint32_t bf[4][4];
            #pragma unroll
            for (int p = 0; p < 4; p++) {
                const int row = wn * 64 + p * 16 + (lane & 15);
                const int seg = s * 2 + (lane >> 4);
                const uint32_t addr = sB + row * 64 + ((seg ^ ((row >> 1) & 3)) << 4);
                asm volatile(
                    "ldmatrix.sync.aligned.m8n8.x4.shared.b16 {%0,%1,%2,%3}, [%4];"
                    : "=r"(bf[p][0]), "=r"(bf[p][1]), "=r"(bf[p][2]), "=r"(bf[p][3])
                    : "r"(addr));
            }
            #pragma unroll
            for (int mt = 0; mt < 2; mt++)
                #pragma unroll
                for (int nt = 0; nt < 8; nt++) {
                    const int p = nt >> 1, hi = nt & 1;
                    asm volatile(
                        "mma.sync.aligned.m16n8k16.row.col.f32.f16.f16.f32 "
                        "{%0,%1,%2,%3}, {%4,%5,%6,%7}, {%8,%9}, {%0,%1,%2,%3};"
                        : "+f"(c[mt][nt][0]), "+f"(c[mt][nt][1]),
                          "+f"(c[mt][nt][2]), "+f"(c[mt][nt][3])
                        : "r"(af[mt][0]), "r"(af[mt][1]), "r"(af[mt][2]), "r"(af[mt][3]),
                          "r"(bf[p][hi]), "r"(bf[p][hi + 2]));
                }
        }
        __syncthreads();
    }

    // ---- Epilogue: global H stores + smem stage (rows < 125 only) ----
    #pragma unroll
    for (int mt = 0; mt < 2; mt++) {
        #pragma unroll
        for (int nt = 0; nt < 8; nt++) {
            const int lr0  = wm * 32 + mt * 16 + g;     // <= 119, always valid
            const int lcol = wn * 64 + nt * 8 + t4 * 2; // tile-local col 0..127
            __half2 v0 = __floats2half2_rn(c[mt][nt][0], c[mt][nt][1]);
            __half2 v1 = __floats2half2_rn(c[mt][nt][2], c[mt][nt][3]);
            *(__half2*)(H + (size_t)(bm + lr0) * SNN_O + bn + lcol) = v0;
            *(__half2*)(&Hst[lr0 * 128 + lcol]) = v0;
            const int lr1 = lr0 + 8;
            if (lr1 < MTILE) {
                *(__half2*)(H + (size_t)(bm + lr1) * SNN_O + bn + lcol) = v1;
                *(__half2*)(&Hst[lr1 * 128 + lcol]) = v1;
            }
        }
    }
    __syncthreads();

    // ---- Fused phase-1: local chunk scan over the 125 staged rows ----
    if (tid < 128) {
        const __half* cp = &Hst[tid];
        float f = 0.0f, o = 0.0f;
        #pragma unroll 1
        for (int t = 0; t < MTILE; t += 5) {
            float v[5];
            #pragma unroll
            for (int j = 0; j < 5; j++)
                v[j] = __half2float(cp[(t + j) * 128]);
            #pragma unroll
            for (int j = 0; j < 5; j++) {
                float nf = fmaf(ALPHA, f, v[j]);
                o = fmaf(BETA, o, f);
                f = nf;
            }
        }
        const int b    = blockIdx.x >> 3;
        const int cidx = blockIdx.x & 7;
        g_end[((b * CHUNKS + cidx) << 8) | (bn + tid)] = make_float2(f, o);
    }
}

// ===========================================================================
// Kernel 2: fused combine + rescan. Each thread: 2 chains (o = 2*o2, 2*o2+1),
// self-combines predecessor chunk states, then rescans its chunk writing out.
// ===========================================================================
__global__ __launch_bounds__(256)
void snn_scan_phase3(const __half* __restrict__ H, float* __restrict__ out)
{
    const int idx  = blockIdx.x * blockDim.x + threadIdx.x;  // 0..65535
    const int o2   = idx & 127;
    const int rest = idx >> 7;
    const int cidx = rest & 7;
    const int b    = rest >> 3;

    // M^CHUNK_L = [[aL,0],[cL,bL]]
    const float aL = exp2f((float)CHUNK_L * log2f(ALPHA));
    const float bL = exp2f((float)CHUNK_L * log2f(BETA));
    const float cL = (aL - bL) / (ALPHA - BETA);

    // self-combine chunk states 0..cidx-1 (uniform per warp, no divergence)
    float f0 = 0.f, o0 = 0.f, f1 = 0.f, o1 = 0.f;
    for (int c2 = 0; c2 < cidx; c2++) {
        const float4 e = *(const float4*)&g_end[((b * CHUNKS + c2) << 8) | (o2 * 2)];
        float nf0 = fmaf(aL, f0, e.x);
        float no0 = fmaf(bL, o0, fmaf(cL, f0, e.y));
        float nf1 = fmaf(aL, f1, e.z);
        float no1 = fmaf(bL, o1, fmaf(cL, f1, e.w));
        f0 = nf0; o0 = no0; f1 = nf1; o1 = no1;
    }

    const size_t ebase = ((size_t)b * SNN_T + cidx * CHUNK_L) * SNN_O + o2 * 2;
    const __half* hp = H + ebase;
    float*        op = out + ebase;

    #pragma unroll 1
    for (int t = 0; t < CHUNK_L; t += 5) {
        __half2 v[5];
        #pragma unroll
        for (int j = 0; j < 5; j++)
            v[j] = *(const __half2*)(hp + (size_t)(t + j) * SNN_O);
        #pragma unroll
        for (int j = 0; j < 5; j++) {
            float h0 = __low2float(v[j]), h1 = __high2float(v[j]);
            float n0 = fmaf(ALPHA, f0, h0);
            float n1 = fmaf(ALPHA, f1, h1);
            o0 = fmaf(BETA, o0, f0);
            o1 = fmaf(BETA, o1, f1);
            f0 = n0; f1 = n1;
            float2 w = {o0, o1};
            *(float2*)(op + (size_t)(t + j) * SNN_O) = w;
        }
    }
}

// ---------------------------------------------------------------------------
extern "C" void kernel_launch(void* const* d_in, const int* in_sizes, int n_in,
                              void* d_out, int out_size)
{
    const float* inputs = (const float*)d_in[0];   // (B, T, I)
    const float* W      = (const float*)d_in[1];   // (O, I)
    float* out = (float*)d_out;                    // (B, T, O) fp32

    __half* h;
    cudaGetSymbolAddress((void**)&h, g_h);

    dim3 gemm_grid(MROWS / MTILE, SNN_O / GBN);    // (512, 2)
    snn_gemm_f16<<<gemm_grid, 256>>>(inputs, W, h);

    const int p3threads = CHAINS * CHUNKS / 2;     // 65536
    snn_scan_phase3<<<p3threads / 256, 256>>>(h, out);
}